// round 5
// baseline (speedup 1.0000x reference)
#include <cuda_runtime.h>
#include <math.h>
#include <stdint.h>

#define N_PTS 8192
#define D_DIM 256
#define NUM_CLS 64
#define EPSF  1e-10f

#define BT 128                    // CTA tile M = N
#define BK 32                     // K chunk
#define NCHUNK (D_DIM / BK)       // 8
#define NSTAGE 3
#define LDA 36                    // padded row stride (floats)
#define ABUF (BT * LDA)           // floats per operand per stage
#define N_TILES (N_PTS / BT)      // 64
#define N_CTAS (N_TILES * (N_TILES + 1) / 2)  // 2080

__device__ float g_sq[N_PTS];
__device__ float g_pos[N_PTS];
__device__ float g_neg[N_PTS];
__device__ int   g_cls[N_PTS];
__device__ int   g_tgt_is64;
__device__ int   g_done = 0;

static __device__ __forceinline__ uint32_t smem_u32(const void* p) {
    uint32_t a;
    asm("{ .reg .u64 t; cvta.to.shared.u64 t, %1; cvt.u32.u64 %0, t; }"
        : "=r"(a) : "l"(p));
    return a;
}
static __device__ __forceinline__ void cp16(uint32_t dst, const void* src) {
    asm volatile("cp.async.cg.shared.global [%0], [%1], 16;"
                 :: "r"(dst), "l"(src) : "memory");
}
#define CP_COMMIT() asm volatile("cp.async.commit_group;" ::: "memory")
#define CP_WAIT(n)  asm volatile("cp.async.wait_group %0;" :: "n"(n) : "memory")

static __device__ __forceinline__ void ldsm4(uint32_t* r, uint32_t addr) {
    asm volatile("ldmatrix.sync.aligned.m8n8.x4.shared.b16 {%0,%1,%2,%3}, [%4];"
                 : "=r"(r[0]), "=r"(r[1]), "=r"(r[2]), "=r"(r[3]) : "r"(addr));
}
static __device__ __forceinline__ void mma_tf32(float* c, const uint32_t* a,
                                                const uint32_t* b) {
    asm volatile(
        "mma.sync.aligned.m16n8k8.row.col.f32.tf32.tf32.f32 "
        "{%0,%1,%2,%3}, {%4,%5,%6,%7}, {%8,%9}, {%0,%1,%2,%3};"
        : "+f"(c[0]), "+f"(c[1]), "+f"(c[2]), "+f"(c[3])
        : "r"(a[0]), "r"(a[1]), "r"(a[2]), "r"(a[3]), "r"(b[0]), "r"(b[1]));
}

// ---------------------------------------------------------------------------
// Kernel 0: detect target dtype (int32 vs int64) without OOB reads.
// ---------------------------------------------------------------------------
__global__ void detect_kernel(const long long* __restrict__ t) {
    __shared__ int bad;
    if (threadIdx.x == 0) bad = 0;
    __syncthreads();
    for (int i = threadIdx.x; i < N_PTS / 2; i += blockDim.x) {
        long long v = t[i];
        if (v < 0 || v >= (long long)NUM_CLS) bad = 1;  // benign race
    }
    __syncthreads();
    if (threadIdx.x == 0) g_tgt_is64 = !bad;
}

// ---------------------------------------------------------------------------
// Kernel 1: squared norms, class load (dtype-adaptive), zero accumulators.
// ---------------------------------------------------------------------------
__global__ void prep_kernel(const float* __restrict__ pred,
                            const void* __restrict__ tgt) {
    int warp = (blockIdx.x * blockDim.x + threadIdx.x) >> 5;
    int lane = threadIdx.x & 31;
    if (warp >= N_PTS) return;
    const float4* row = (const float4*)(pred + (size_t)warp * D_DIM);
    float s = 0.f;
#pragma unroll
    for (int q = 0; q < 2; ++q) {
        float4 v = row[lane + 32 * q];
        s += v.x * v.x + v.y * v.y + v.z * v.z + v.w * v.w;
    }
#pragma unroll
    for (int o = 16; o; o >>= 1) s += __shfl_xor_sync(0xffffffffu, s, o);
    if (lane == 0) {
        g_sq[warp]  = s;
        g_pos[warp] = 0.f;
        g_neg[warp] = 0.f;
        int c;
        if (g_tgt_is64) c = (int)((const long long*)tgt)[warp];
        else            c = ((const int*)tgt)[warp];
        g_cls[warp] = c;
    }
}

// ---------------------------------------------------------------------------
// Kernel 2: tf32 mma.sync Gram tile + fused epilogue + folded finalize.
// Triangular 1D grid; ldmatrix fragments; 3-stage cp.async pipeline.
// ---------------------------------------------------------------------------
__global__ __launch_bounds__(256, 2)
void tile_kernel(const float* __restrict__ pred,
                 const float* __restrict__ tempPtr,
                 float* __restrict__ out) {
    // decode triangular index t -> (bi, bj), bi <= bj
    int t = blockIdx.x;
    int bi = (int)((129.0f - sqrtf(16641.0f - 8.0f * (float)t)) * 0.5f);
    while ((bi + 1) * (129 - (bi + 1)) / 2 <= t) ++bi;
    while (bi * (129 - bi) / 2 > t) --bi;
    int bj = bi + (t - bi * (129 - bi) / 2);

    extern __shared__ float sm[];                 // [NSTAGE][2][ABUF] + aux
    float* sqR = sm + NSTAGE * 2 * ABUF;
    float* sqC = sqR + BT;
    int*   clR = (int*)(sqC + BT);
    int*   clC = clR + BT;
    uint32_t sbase = smem_u32(sm);

    int tid  = threadIdx.x;
    int lane = tid & 31, wid = tid >> 5;
    int wm = wid & 1, wn = wid >> 1;              // 2 x 4 warp grid
    int R0 = wm * 64, C0 = wn * 32;
    int gq = lane >> 2, tq = lane & 3;
    int i0 = bi * BT, j0 = bj * BT;

    if (tid < BT) {
        sqR[tid] = g_sq[i0 + tid];
        sqC[tid] = g_sq[j0 + tid];
        clR[tid] = g_cls[i0 + tid];
        clC[tid] = g_cls[j0 + tid];
    }

    // per-thread ldmatrix byte offsets (within an operand stage)
    uint32_t offA = (uint32_t)(((R0 + (lane & 15)) * LDA + (lane >> 4) * 4) * 4);
    uint32_t offB = (uint32_t)(((C0 + (lane >> 4) * 8 + (lane & 7)) * LDA
                                + ((lane >> 3) & 1) * 4) * 4);

    float acc[4][4][4];
#pragma unroll
    for (int mi = 0; mi < 4; mi++)
#pragma unroll
        for (int ni = 0; ni < 4; ni++)
#pragma unroll
            for (int v = 0; v < 4; v++) acc[mi][ni][v] = 0.f;

    auto issue = [&](int stage, int k0) {
        uint32_t sA = sbase + (uint32_t)(stage * 2 * ABUF) * 4u;
        uint32_t sB = sA + (uint32_t)ABUF * 4u;
#pragma unroll
        for (int i = 0; i < 4; ++i) {
            int f = tid + i * 256;                // 0..1023
            int row = f >> 3, q = f & 7;          // 8 x float4 per row
            uint32_t off = (uint32_t)(row * LDA + q * 4) * 4u;
            cp16(sA + off, pred + (size_t)(i0 + row) * D_DIM + k0 + q * 4);
            cp16(sB + off, pred + (size_t)(j0 + row) * D_DIM + k0 + q * 4);
        }
        CP_COMMIT();
    };

    issue(0, 0);
    issue(1, BK);
#pragma unroll 1
    for (int c = 0; c < NCHUNK; ++c) {
        if (c < NCHUNK - 1) CP_WAIT(1); else CP_WAIT(0);
        __syncthreads();
        if (c + 2 < NCHUNK) issue((c + 2) % NSTAGE, (c + 2) * BK);

        uint32_t sA = sbase + (uint32_t)((c % NSTAGE) * 2 * ABUF) * 4u;
        uint32_t sB = sA + (uint32_t)ABUF * 4u;
#pragma unroll
        for (int ks = 0; ks < 4; ++ks) {
            uint32_t a[4][4], b[4][2];
#pragma unroll
            for (int mi = 0; mi < 4; mi++)
                ldsm4(a[mi], sA + offA + (uint32_t)((mi * 16 * LDA + ks * 8) * 4));
#pragma unroll
            for (int p = 0; p < 2; p++) {
                uint32_t r[4];
                ldsm4(r, sB + offB + (uint32_t)((p * 16 * LDA + ks * 8) * 4));
                b[2 * p][0] = r[0]; b[2 * p][1] = r[1];
                b[2 * p + 1][0] = r[2]; b[2 * p + 1][1] = r[3];
            }
#pragma unroll
            for (int mi = 0; mi < 4; mi++)
#pragma unroll
                for (int ni = 0; ni < 4; ni++)
                    mma_tf32(acc[mi][ni], a[mi], b[ni]);
        }
    }

    // ---- Epilogue: exp + masked sums on register fragments ----
    float invT = 1.0f / tempPtr[0];
    bool diag  = (bi == bj);

    float rP[8], rN[8], cP[8], cN[8];
#pragma unroll
    for (int q = 0; q < 8; q++) { rP[q] = rN[q] = cP[q] = cN[q] = 0.f; }

#pragma unroll
    for (int mi = 0; mi < 4; mi++)
#pragma unroll
        for (int h = 0; h < 2; h++) {
            int rl = R0 + mi * 16 + gq + h * 8;
            float sqi = sqR[rl];
            int   ci  = clR[rl];
#pragma unroll
            for (int ni = 0; ni < 4; ni++)
#pragma unroll
                for (int w = 0; w < 2; w++) {
                    int cl = C0 + ni * 8 + tq * 2 + w;
                    float dot = acc[mi][ni][h * 2 + w];
                    float pn  = fmaxf(sqi + sqC[cl] - 2.0f * dot, EPSF);
                    float dv  = __expf(-pn * invT);
                    if (diag && rl == cl) dv = 0.f;
                    bool same = (ci == clC[cl]);
                    float p = same ? dv : 0.f;
                    float n = dv - p;
                    rP[mi * 2 + h] += p; rN[mi * 2 + h] += n;
                    cP[ni * 2 + w] += p; cN[ni * 2 + w] += n;
                }
        }

#pragma unroll
    for (int q = 0; q < 8; q++) {
#pragma unroll
        for (int o = 4; o <= 16; o <<= 1) {
            cP[q] += __shfl_xor_sync(0xffffffffu, cP[q], o);
            cN[q] += __shfl_xor_sync(0xffffffffu, cN[q], o);
        }
    }
    if (lane < 4) {
#pragma unroll
        for (int q = 0; q < 8; q++) {
            int cl = C0 + (q >> 1) * 8 + lane * 2 + (q & 1);
            atomicAdd(&g_pos[j0 + cl], cP[q]);
            atomicAdd(&g_neg[j0 + cl], cN[q]);
        }
    }
#pragma unroll
    for (int q = 0; q < 8; q++) {
#pragma unroll
        for (int o = 1; o <= 2; o <<= 1) {
            rP[q] += __shfl_xor_sync(0xffffffffu, rP[q], o);
            rN[q] += __shfl_xor_sync(0xffffffffu, rN[q], o);
        }
    }
    if (!diag && tq == 0) {
#pragma unroll
        for (int q = 0; q < 8; q++) {
            int rl = R0 + (q >> 1) * 16 + gq + (q & 1) * 8;
            atomicAdd(&g_pos[i0 + rl], rP[q]);
            atomicAdd(&g_neg[i0 + rl], rN[q]);
        }
    }

    // ---- Folded finalize: last CTA to finish reduces the loss ----
    __shared__ int s_last;
    __syncthreads();
    if (tid == 0) {
        __threadfence();
        s_last = (atomicAdd(&g_done, 1) == N_CTAS - 1);
    }
    __syncthreads();
    if (s_last) {
        __threadfence();
        __shared__ float red[8];
        float s = 0.f;
        for (int j = tid; j < N_PTS; j += 256) {
            float num = g_pos[j];
            float den = fmaxf(g_neg[j], EPSF);
            float frac = num / (num + den);
            if (frac >= EPSF) s += logf(frac);
        }
#pragma unroll
        for (int o = 16; o; o >>= 1) s += __shfl_xor_sync(0xffffffffu, s, o);
        if (lane == 0) red[wid] = s;
        __syncthreads();
        if (tid < 8) {
            float v = red[tid];
#pragma unroll
            for (int o = 4; o; o >>= 1) v += __shfl_xor_sync(0xffu, v, o);
            if (tid == 0) {
                out[0] = -v / (float)N_PTS;
                g_done = 0;   // reset for deterministic graph replay
            }
        }
    }
}

// ---------------------------------------------------------------------------
extern "C" void kernel_launch(void* const* d_in, const int* in_sizes, int n_in,
                              void* d_out, int out_size) {
    const float* pred = (const float*)d_in[0];
    const void*  tgt  = d_in[1];
    const float* temp = (const float*)d_in[2];

    const int smem_bytes = (NSTAGE * 2 * ABUF) * 4 + 2 * BT * 4 + 2 * BT * 4;
    cudaFuncSetAttribute(tile_kernel,
                         cudaFuncAttributeMaxDynamicSharedMemorySize, smem_bytes);

    detect_kernel<<<1, 256>>>((const long long*)tgt);
    prep_kernel<<<(N_PTS * 32 + 255) / 256, 256>>>(pred, tgt);
    tile_kernel<<<N_CTAS, 256, smem_bytes>>>(pred, temp, (float*)d_out);
}